// round 1
// baseline (speedup 1.0000x reference)
#include <cuda_runtime.h>
#include <math.h>

#define NB 64
#define NPIX 596
#define HEADS 4
#define DH 64
#define TI 16
#define PER_B (HEADS*NPIX*DH)   // 152576

// ---------------- scratch (device globals, no allocation) ----------------
__device__ float g_conv1[NB*16*150*5];
__device__ float g_feats[NB*NPIX*34];
__device__ float g_K[NB*HEADS*NPIX*DH];
__device__ float g_Q[NB*HEADS*NPIX*DH];
__device__ float g_V[NB*HEADS*NPIX*DH];
__device__ float g_mu[3*NB], g_rv[3*NB];
__device__ float g_E[NB*NPIX*256];
__device__ float g_F[NB*NPIX*DH];
__device__ float g_mu2[NB], g_rv2[NB];
__device__ float g_M[NB*DH];

__device__ __forceinline__ float eluf(float x) {
    return x > 0.f ? x : (expf(x) - 1.f);
}

// ---------------- conv1 + relu ----------------
__global__ void conv1_kernel(const float* __restrict__ x,
                             const float* __restrict__ w,
                             const float* __restrict__ b) {
    int idx = blockIdx.x * blockDim.x + threadIdx.x;
    if (idx >= NB*16*150*5) return;
    int ow = idx % 5;
    int oh = (idx / 5) % 150;
    int co = (idx / (5*150)) % 16;
    int bb = idx / (5*150*16);
    float acc = b[co];
    #pragma unroll
    for (int ci = 0; ci < 4; ci++)
        #pragma unroll
        for (int kh = 0; kh < 2; kh++)
            #pragma unroll
            for (int kw = 0; kw < 2; kw++)
                acc += x[((bb*4+ci)*151 + oh+kh)*6 + ow+kw] *
                       w[((co*4+ci)*2 + kh)*2 + kw];
    g_conv1[idx] = fmaxf(acc, 0.f);
}

// ---------------- conv2 + relu + coords -> feats (N, 596, 34) ----------------
__global__ void conv2_feats_kernel(const float* __restrict__ w,
                                   const float* __restrict__ b) {
    int idx = blockIdx.x * blockDim.x + threadIdx.x;
    if (idx >= NB*NPIX*34) return;
    int c = idx % 34;
    int p = (idx / 34) % NPIX;
    int bb = idx / (34*NPIX);
    int oh = p / 4, ow = p % 4;
    float val;
    if (c < 32) {
        float acc = b[c];
        #pragma unroll 4
        for (int ci = 0; ci < 16; ci++)
            #pragma unroll
            for (int kh = 0; kh < 2; kh++)
                #pragma unroll
                for (int kw = 0; kw < 2; kw++)
                    acc += g_conv1[((bb*16+ci)*150 + oh+kh)*5 + ow+kw] *
                           w[((c*16+ci)*2 + kh)*2 + kw];
        val = fmaxf(acc, 0.f);
    } else if (c == 32) {
        val = (float)ow / 4.f;
    } else {
        val = (float)oh / 149.f;
    }
    g_feats[idx] = val;
}

// ---------------- K/Q/V projections (b,p,hd) -> [b][h][p][d] ----------------
__global__ void proj_kernel(const float* __restrict__ kw, const float* __restrict__ kb,
                            const float* __restrict__ qw, const float* __restrict__ qb,
                            const float* __restrict__ vw, const float* __restrict__ vb) {
    int t = blockIdx.y;
    const float* W = t==0 ? kw : t==1 ? qw : vw;
    const float* B = t==0 ? kb : t==1 ? qb : vb;
    float* O = t==0 ? g_K : t==1 ? g_Q : g_V;
    int idx = blockIdx.x * blockDim.x + threadIdx.x;
    if (idx >= NB*NPIX*256) return;
    int hd = idx & 255;
    int bp = idx >> 8;
    int p = bp % NPIX, bb = bp / NPIX;
    const float* f = g_feats + bp*34;
    float acc = B[hd];
    #pragma unroll
    for (int c = 0; c < 34; c++) acc += f[c] * W[c*256 + hd];
    int h = hd >> 6, d = hd & 63;
    O[((bb*HEADS + h)*NPIX + p)*DH + d] = acc;
}

// ---------------- LN stats over (h,p,d) per batch ----------------
__global__ void ln_stats_kernel() {
    int bb = blockIdx.x, t = blockIdx.y;
    const float* base = (t==0 ? g_K : t==1 ? g_Q : g_V) + bb*PER_B;
    double s = 0.0, ss = 0.0;
    for (int i = threadIdx.x; i < PER_B; i += blockDim.x) {
        double v = base[i]; s += v; ss += v*v;
    }
    __shared__ double sh[256], sh2[256];
    sh[threadIdx.x] = s; sh2[threadIdx.x] = ss; __syncthreads();
    for (int o = 128; o; o >>= 1) {
        if (threadIdx.x < o) { sh[threadIdx.x] += sh[threadIdx.x+o]; sh2[threadIdx.x] += sh2[threadIdx.x+o]; }
        __syncthreads();
    }
    if (threadIdx.x == 0) {
        double m = sh[0] / (double)PER_B;
        double var = sh2[0] / (double)PER_B - m*m;
        g_mu[t*NB+bb] = (float)m;
        g_rv[t*NB+bb] = (float)(1.0 / sqrt(var + 1e-5));
    }
}

// ---------------- LN apply (with affine g,b) in place ----------------
__global__ void ln_apply_kernel(const float* __restrict__ kg, const float* __restrict__ kb,
                                const float* __restrict__ qg, const float* __restrict__ qb,
                                const float* __restrict__ vg, const float* __restrict__ vb) {
    int t = blockIdx.y;
    float* base = t==0 ? g_K : t==1 ? g_Q : g_V;
    const float* g = t==0 ? kg : t==1 ? qg : vg;
    const float* be = t==0 ? kb : t==1 ? qb : vb;
    int n = NB * PER_B;
    for (int i = blockIdx.x*blockDim.x + threadIdx.x; i < n; i += gridDim.x*blockDim.x) {
        int bb = i / PER_B, off = i % PER_B;
        base[i] = (base[i] - g_mu[t*NB+bb]) * g_rv[t*NB+bb] * g[off] + be[off];
    }
}

// ---------------- fused attention: A = elu(Q@qlw + K@klw + bias); S = A@alw + ab;
//                  P = softmax(S); E = P @ V,  written as (b, p, h*64+d) ----------------
__global__ __launch_bounds__(256) void attn_kernel(
    const float* __restrict__ qlw, const float* __restrict__ qlb,
    const float* __restrict__ klw, const float* __restrict__ klb,
    const float* __restrict__ alw, const float* __restrict__ alb) {
    __shared__ float q_s[TI][DH];
    __shared__ float k_s[TI][DH];
    __shared__ float a_s[TI][600];
    int tile = blockIdx.x, h = blockIdx.y, bb = blockIdx.z;
    int p0 = tile * TI;
    int t = threadIdx.x;
    const float* Qb = g_Q + (bb*HEADS + h)*NPIX*DH;
    const float* Kb = g_K + (bb*HEADS + h)*NPIX*DH;
    const float* Vb = g_V + (bb*HEADS + h)*NPIX*DH;

    for (int i = t; i < TI*DH; i += 256) {
        int r = i >> 6, d = i & 63;
        int p = p0 + r;
        q_s[r][d] = (p < NPIX) ? Qb[p*DH + d] : 0.f;
        k_s[r][d] = (p < NPIX) ? Kb[p*DH + d] : 0.f;
    }
    __syncthreads();

    // A stage: logits tile (TI x 596) -> elu -> smem
    for (int j = t; j < NPIX; j += 256) {
        float acc[TI];
        #pragma unroll
        for (int r = 0; r < TI; r++) acc[r] = 0.f;
        #pragma unroll 4
        for (int d = 0; d < DH; d++) {
            float qw = qlw[d*NPIX + j];
            float kw = klw[d*NPIX + j];
            #pragma unroll
            for (int r = 0; r < TI; r++)
                acc[r] += q_s[r][d]*qw + k_s[r][d]*kw;
        }
        float bias = qlb[j] + klb[j];
        #pragma unroll
        for (int r = 0; r < TI; r++)
            a_s[r][j] = eluf(acc[r] + bias);
    }
    __syncthreads();

    // S stage: S = A @ alin_w  (596-deep, 16-row register blocking)
    int j0 = t, j1 = t + 256, j2 = t + 512;
    bool v2 = (j2 < NPIX);
    float s0[TI], s1[TI], s2[TI];
    #pragma unroll
    for (int r = 0; r < TI; r++) { s0[r] = 0.f; s1[r] = 0.f; s2[r] = 0.f; }
    for (int k = 0; k < NPIX; k++) {
        const float* wr = alw + k*NPIX;
        float w0 = wr[j0];
        float w1 = wr[j1];
        float w2 = v2 ? wr[j2] : 0.f;
        #pragma unroll
        for (int r = 0; r < TI; r++) {
            float a = a_s[r][k];
            s0[r] += a*w0; s1[r] += a*w1; s2[r] += a*w2;
        }
    }
    __syncthreads();   // all a_s reads complete before overwrite
    {
        float b0 = alb[j0], b1 = alb[j1], b2 = v2 ? alb[j2] : 0.f;
        #pragma unroll
        for (int r = 0; r < TI; r++) {
            a_s[r][j0] = s0[r] + b0;
            a_s[r][j1] = s1[r] + b1;
            if (v2) a_s[r][j2] = s2[r] + b2;
        }
    }
    __syncthreads();

    // softmax: one warp per row (8 warps x 2 passes)
    int warp = t >> 5, lane = t & 31;
    for (int r = warp; r < TI; r += 8) {
        float m = -1e30f;
        for (int j = lane; j < NPIX; j += 32) m = fmaxf(m, a_s[r][j]);
        #pragma unroll
        for (int o = 16; o; o >>= 1) m = fmaxf(m, __shfl_xor_sync(0xffffffffu, m, o));
        float sum = 0.f;
        for (int j = lane; j < NPIX; j += 32) {
            float e = expf(a_s[r][j] - m);
            a_s[r][j] = e;
            sum += e;
        }
        #pragma unroll
        for (int o = 16; o; o >>= 1) sum += __shfl_xor_sync(0xffffffffu, sum, o);
        float inv = 1.f / sum;
        for (int j = lane; j < NPIX; j += 32) a_s[r][j] *= inv;
    }
    __syncthreads();

    // E stage: E = P @ V. thread -> (d = t&63, row group rg = t>>6)
    int d = t & 63, rg = t >> 6;
    float e[4] = {0.f, 0.f, 0.f, 0.f};
    for (int j = 0; j < NPIX; j++) {
        float v = Vb[j*DH + d];
        #pragma unroll
        for (int q = 0; q < 4; q++)
            e[q] += a_s[rg + 4*q][j] * v;
    }
    #pragma unroll
    for (int q = 0; q < 4; q++) {
        int r = rg + 4*q;
        int p = p0 + r;
        if (p < NPIX)
            g_E[(bb*NPIX + p)*256 + h*DH + d] = e[q];
    }
}

// ---------------- lin1 + relu ----------------
__global__ void lin1_kernel(const float* __restrict__ w, const float* __restrict__ b) {
    int idx = blockIdx.x * blockDim.x + threadIdx.x;
    if (idx >= NB*NPIX*DH) return;
    int d = idx & 63;
    int bp = idx >> 6;
    const float* e = g_E + bp*256;
    float acc = b[d];
    #pragma unroll 8
    for (int c = 0; c < 256; c++) acc += e[c] * w[c*DH + d];
    g_F[idx] = fmaxf(acc, 0.f);
}

// ---------------- LN2 stats (per b over 596*64, no affine) ----------------
__global__ void ln2_stats_kernel() {
    int bb = blockIdx.x;
    const float* base = g_F + bb*NPIX*DH;
    const int n = NPIX*DH;
    double s = 0.0, ss = 0.0;
    for (int i = threadIdx.x; i < n; i += blockDim.x) {
        double v = base[i]; s += v; ss += v*v;
    }
    __shared__ double sh[256], sh2[256];
    sh[threadIdx.x] = s; sh2[threadIdx.x] = ss; __syncthreads();
    for (int o = 128; o; o >>= 1) {
        if (threadIdx.x < o) { sh[threadIdx.x] += sh[threadIdx.x+o]; sh2[threadIdx.x] += sh2[threadIdx.x+o]; }
        __syncthreads();
    }
    if (threadIdx.x == 0) {
        double m = sh[0] / (double)n;
        double var = sh2[0] / (double)n - m*m;
        g_mu2[bb] = (float)m;
        g_rv2[bb] = (float)(1.0 / sqrt(var + 1e-5));
    }
}

// ---------------- LN2 apply + max over pixels ----------------
__global__ void ln2max_kernel() {
    int bb = blockIdx.x, d = threadIdx.x;
    float mu = g_mu2[bb], rv = g_rv2[bb];
    float m = -1e30f;
    for (int p = 0; p < NPIX; p++) {
        float v = (g_F[(bb*NPIX + p)*DH + d] - mu) * rv;
        m = fmaxf(m, v);
    }
    g_M[bb*DH + d] = m;
}

// ---------------- final lin2 + elu ----------------
__global__ void final_kernel(const float* __restrict__ w, const float* __restrict__ b,
                             float* __restrict__ out) {
    int idx = blockIdx.x * blockDim.x + threadIdx.x;
    if (idx >= NB*10) return;
    int bb = idx / 10, j = idx % 10;
    float acc = b[j];
    #pragma unroll
    for (int d = 0; d < DH; d++) acc += g_M[bb*DH + d] * w[d*10 + j];
    out[idx] = eluf(acc);
}

extern "C" void kernel_launch(void* const* d_in, const int* in_sizes, int n_in,
                              void* d_out, int out_size) {
    const float* x       = (const float*)d_in[0];
    const float* conv1_w = (const float*)d_in[1];
    const float* conv1_b = (const float*)d_in[2];
    const float* conv2_w = (const float*)d_in[3];
    const float* conv2_b = (const float*)d_in[4];
    const float* kp_w    = (const float*)d_in[5];
    const float* kp_b    = (const float*)d_in[6];
    const float* qp_w    = (const float*)d_in[7];
    const float* qp_b    = (const float*)d_in[8];
    const float* vp_w    = (const float*)d_in[9];
    const float* vp_b    = (const float*)d_in[10];
    const float* klin_w  = (const float*)d_in[11];
    const float* klin_b  = (const float*)d_in[12];
    const float* qlin_w  = (const float*)d_in[13];
    const float* qlin_b  = (const float*)d_in[14];
    const float* alin_w  = (const float*)d_in[15];
    const float* alin_b  = (const float*)d_in[16];
    const float* knorm_g = (const float*)d_in[17];
    const float* knorm_b = (const float*)d_in[18];
    const float* qnorm_g = (const float*)d_in[19];
    const float* qnorm_b = (const float*)d_in[20];
    const float* vnorm_g = (const float*)d_in[21];
    const float* vnorm_b = (const float*)d_in[22];
    const float* lin1_w  = (const float*)d_in[23];
    const float* lin1_b  = (const float*)d_in[24];
    const float* lin2_w  = (const float*)d_in[25];
    const float* lin2_b  = (const float*)d_in[26];
    float* out = (float*)d_out;

    conv1_kernel<<<(NB*16*150*5 + 255)/256, 256>>>(x, conv1_w, conv1_b);
    conv2_feats_kernel<<<(NB*NPIX*34 + 255)/256, 256>>>(conv2_w, conv2_b);
    {
        dim3 g((NB*NPIX*256 + 255)/256, 3);
        proj_kernel<<<g, 256>>>(kp_w, kp_b, qp_w, qp_b, vp_w, vp_b);
    }
    {
        dim3 g(NB, 3);
        ln_stats_kernel<<<g, 256>>>();
    }
    {
        dim3 g(4096, 3);
        ln_apply_kernel<<<g, 256>>>(knorm_g, knorm_b, qnorm_g, qnorm_b, vnorm_g, vnorm_b);
    }
    {
        dim3 g((NPIX + TI - 1)/TI, HEADS, NB);  // (38, 4, 64)
        attn_kernel<<<g, 256>>>(qlin_w, qlin_b, klin_w, klin_b, alin_w, alin_b);
    }
    lin1_kernel<<<(NB*NPIX*DH + 255)/256, 256>>>(lin1_w, lin1_b);
    ln2_stats_kernel<<<NB, 256>>>();
    ln2max_kernel<<<NB, DH>>>();
    final_kernel<<<3, 256>>>(lin2_w, lin2_b, out);
}

// round 2
// speedup vs baseline: 2.2775x; 2.2775x over previous
#include <cuda_runtime.h>
#include <math.h>

#define NB 64
#define NPIX 596
#define HEADS 4
#define DH 64
#define PER_B (HEADS*NPIX*DH)   // 152576

#define TI2 32
#define ATHR 320
#define APAD 36
#define SMEM_FLOATS (NPIX*APAD + 2*DH*APAD)   // 21456 + 4608 = 26064
#define SMEM_BYTES (SMEM_FLOATS*4)            // 104256

// ---------------- scratch (device globals, no allocation) ----------------
__device__ float g_conv1[NB*16*150*5];
__device__ float g_feats[NB*NPIX*34];
__device__ float g_K[NB*HEADS*NPIX*DH];
__device__ float g_Q[NB*HEADS*NPIX*DH];
__device__ float g_V[NB*HEADS*NPIX*DH];
__device__ float g_mu[3*NB], g_rv[3*NB];
__device__ float g_E[NB*NPIX*256];
__device__ float g_F[NB*NPIX*DH];
__device__ float g_mu2[NB], g_rv2[NB];
__device__ float g_M[NB*DH];

__device__ __forceinline__ float eluf(float x) {
    return x > 0.f ? x : (__expf(x) - 1.f);
}

// packed fp32x2 helpers (sm_103a)
__device__ __forceinline__ void ffma2(unsigned long long &acc,
                                      unsigned long long a,
                                      unsigned long long b) {
    asm("fma.rn.f32x2 %0, %1, %2, %0;" : "+l"(acc) : "l"(a), "l"(b));
}
__device__ __forceinline__ unsigned long long dup2(float x) {
    unsigned long long r;
    asm("mov.b64 %0, {%1, %1};" : "=l"(r) : "f"(x));
    return r;
}
__device__ __forceinline__ float lo2(unsigned long long v) {
    float a, b;
    asm("mov.b64 {%0, %1}, %2;" : "=f"(a), "=f"(b) : "l"(v));
    return a;
}
__device__ __forceinline__ float hi2(unsigned long long v) {
    float a, b;
    asm("mov.b64 {%0, %1}, %2;" : "=f"(a), "=f"(b) : "l"(v));
    return b;
}

// ---------------- conv1 + relu ----------------
__global__ void conv1_kernel(const float* __restrict__ x,
                             const float* __restrict__ w,
                             const float* __restrict__ b) {
    int idx = blockIdx.x * blockDim.x + threadIdx.x;
    if (idx >= NB*16*150*5) return;
    int ow = idx % 5;
    int oh = (idx / 5) % 150;
    int co = (idx / (5*150)) % 16;
    int bb = idx / (5*150*16);
    float acc = b[co];
    #pragma unroll
    for (int ci = 0; ci < 4; ci++)
        #pragma unroll
        for (int kh = 0; kh < 2; kh++)
            #pragma unroll
            for (int kw = 0; kw < 2; kw++)
                acc += x[((bb*4+ci)*151 + oh+kh)*6 + ow+kw] *
                       w[((co*4+ci)*2 + kh)*2 + kw];
    g_conv1[idx] = fmaxf(acc, 0.f);
}

// ---------------- conv2 + relu + coords -> feats (N, 596, 34) ----------------
__global__ void conv2_feats_kernel(const float* __restrict__ w,
                                   const float* __restrict__ b) {
    int idx = blockIdx.x * blockDim.x + threadIdx.x;
    if (idx >= NB*NPIX*34) return;
    int c = idx % 34;
    int p = (idx / 34) % NPIX;
    int bb = idx / (34*NPIX);
    int oh = p / 4, ow = p % 4;
    float val;
    if (c < 32) {
        float acc = b[c];
        #pragma unroll 4
        for (int ci = 0; ci < 16; ci++)
            #pragma unroll
            for (int kh = 0; kh < 2; kh++)
                #pragma unroll
                for (int kw = 0; kw < 2; kw++)
                    acc += g_conv1[((bb*16+ci)*150 + oh+kh)*5 + ow+kw] *
                           w[((c*16+ci)*2 + kh)*2 + kw];
        val = fmaxf(acc, 0.f);
    } else if (c == 32) {
        val = (float)ow / 4.f;
    } else {
        val = (float)oh / 149.f;
    }
    g_feats[idx] = val;
}

// ---------------- K/Q/V projections (b,p,hd) -> [b][h][p][d] ----------------
__global__ void proj_kernel(const float* __restrict__ kw, const float* __restrict__ kb,
                            const float* __restrict__ qw, const float* __restrict__ qb,
                            const float* __restrict__ vw, const float* __restrict__ vb) {
    int t = blockIdx.y;
    const float* W = t==0 ? kw : t==1 ? qw : vw;
    const float* B = t==0 ? kb : t==1 ? qb : vb;
    float* O = t==0 ? g_K : t==1 ? g_Q : g_V;
    int idx = blockIdx.x * blockDim.x + threadIdx.x;
    if (idx >= NB*NPIX*256) return;
    int hd = idx & 255;
    int bp = idx >> 8;
    int p = bp % NPIX, bb = bp / NPIX;
    const float* f = g_feats + bp*34;
    float acc = B[hd];
    #pragma unroll
    for (int c = 0; c < 34; c++) acc += f[c] * W[c*256 + hd];
    int h = hd >> 6, d = hd & 63;
    O[((bb*HEADS + h)*NPIX + p)*DH + d] = acc;
}

// ---------------- LN stats over (h,p,d) per batch (float accum) ----------------
__global__ void ln_stats_kernel() {
    int bb = blockIdx.x, t = blockIdx.y;
    const float* base = (t==0 ? g_K : t==1 ? g_Q : g_V) + bb*PER_B;
    float s = 0.f, ss = 0.f;
    for (int i = threadIdx.x; i < PER_B; i += blockDim.x) {
        float v = base[i]; s += v; ss += v*v;
    }
    __shared__ double sh[256], sh2[256];
    sh[threadIdx.x] = (double)s; sh2[threadIdx.x] = (double)ss; __syncthreads();
    for (int o = 128; o; o >>= 1) {
        if (threadIdx.x < o) { sh[threadIdx.x] += sh[threadIdx.x+o]; sh2[threadIdx.x] += sh2[threadIdx.x+o]; }
        __syncthreads();
    }
    if (threadIdx.x == 0) {
        double m = sh[0] / (double)PER_B;
        double var = sh2[0] / (double)PER_B - m*m;
        g_mu[t*NB+bb] = (float)m;
        g_rv[t*NB+bb] = (float)(1.0 / sqrt(var + 1e-5));
    }
}

// ---------------- LN apply (with affine g,b) in place ----------------
__global__ void ln_apply_kernel(const float* __restrict__ kg, const float* __restrict__ kb,
                                const float* __restrict__ qg, const float* __restrict__ qb,
                                const float* __restrict__ vg, const float* __restrict__ vb) {
    int t = blockIdx.y;
    float* base = t==0 ? g_K : t==1 ? g_Q : g_V;
    const float* g = t==0 ? kg : t==1 ? qg : vg;
    const float* be = t==0 ? kb : t==1 ? qb : vb;
    int n = NB * PER_B;
    for (int i = blockIdx.x*blockDim.x + threadIdx.x; i < n; i += gridDim.x*blockDim.x) {
        int bb = i / PER_B, off = i % PER_B;
        base[i] = (base[i] - g_mu[t*NB+bb]) * g_rv[t*NB+bb] * g[off] + be[off];
    }
}

// ---------------- fused attention, TI2=32 rows per block, packed f32x2 ----------------
// smem layout (dynamic): a_t[596][36] (A transposed: [col][row]), q_t[64][36], k_t[64][36]
__global__ __launch_bounds__(ATHR, 2) void attn_kernel(
    const float* __restrict__ qlw, const float* __restrict__ qlb,
    const float* __restrict__ klw, const float* __restrict__ klb,
    const float* __restrict__ alw, const float* __restrict__ alb) {
    extern __shared__ float smem[];
    float* a_t = smem;                     // [NPIX][APAD]  element [j][r]
    float* q_t = smem + NPIX*APAD;         // [DH][APAD]    element [d][r]
    float* k_t = q_t + DH*APAD;

    int tile = blockIdx.x, h = blockIdx.y, bb = blockIdx.z;
    int p0 = tile * TI2;
    int t = threadIdx.x;
    const float* Qb = g_Q + (bb*HEADS + h)*NPIX*DH;
    const float* Kb = g_K + (bb*HEADS + h)*NPIX*DH;
    const float* Vb = g_V + (bb*HEADS + h)*NPIX*DH;

    // load Q,K tile transposed: q_t[d][r]
    for (int i = t; i < TI2*DH; i += ATHR) {
        int r = i >> 6, d = i & 63;
        int p = p0 + r;
        q_t[d*APAD + r] = (p < NPIX) ? Qb[p*DH + d] : 0.f;
        k_t[d*APAD + r] = (p < NPIX) ? Kb[p*DH + d] : 0.f;
    }
    __syncthreads();

    // ---- A stage: logits -> elu -> a_t[j][r]. thread handles cols t and 320+t ----
    for (int c = 0; c < 2; c++) {
        if (c == 1 && t >= NPIX - ATHR) break;   // t >= 276
        int j = c == 0 ? t : ATHR + t;
        unsigned long long acc[TI2/2];
        #pragma unroll
        for (int rp = 0; rp < TI2/2; rp++) acc[rp] = 0ull;
        #pragma unroll 4
        for (int d = 0; d < DH; d++) {
            unsigned long long qw2 = dup2(qlw[d*NPIX + j]);
            unsigned long long kw2 = dup2(klw[d*NPIX + j]);
            const unsigned long long* qp = (const unsigned long long*)(q_t + d*APAD);
            const unsigned long long* kp = (const unsigned long long*)(k_t + d*APAD);
            #pragma unroll
            for (int rp = 0; rp < TI2/2; rp++) {
                ffma2(acc[rp], qp[rp], qw2);
                ffma2(acc[rp], kp[rp], kw2);
            }
        }
        float bias = qlb[j] + klb[j];
        float2* arow = (float2*)(a_t + j*APAD);
        #pragma unroll
        for (int rp = 0; rp < TI2/2; rp++) {
            float2 o;
            o.x = eluf(lo2(acc[rp]) + bias);
            o.y = eluf(hi2(acc[rp]) + bias);
            arow[rp] = o;
        }
    }
    __syncthreads();

    // ---- S stage: S = A @ alin_w (packed rows). thread owns cols j0=t, j1=320+t ----
    {
        int j0 = t, j1 = ATHR + t;
        bool has1 = (t < NPIX - ATHR);
        unsigned long long s0[TI2/2], s1[TI2/2];
        #pragma unroll
        for (int rp = 0; rp < TI2/2; rp++) { s0[rp] = 0ull; s1[rp] = 0ull; }
        for (int k = 0; k < NPIX; k++) {
            const unsigned long long* ar = (const unsigned long long*)(a_t + k*APAD);
            unsigned long long w0 = dup2(alw[k*NPIX + j0]);
            unsigned long long w1 = has1 ? dup2(alw[k*NPIX + j1]) : 0ull;
            #pragma unroll
            for (int rp = 0; rp < TI2/2; rp++) {
                unsigned long long a = ar[rp];
                ffma2(s0[rp], a, w0);
                ffma2(s1[rp], a, w1);
            }
        }
        __syncthreads();   // done reading a_t, safe to overwrite
        float b0 = alb[j0];
        float2* r0 = (float2*)(a_t + j0*APAD);
        #pragma unroll
        for (int rp = 0; rp < TI2/2; rp++) {
            float2 o; o.x = lo2(s0[rp]) + b0; o.y = hi2(s0[rp]) + b0;
            r0[rp] = o;
        }
        if (has1) {
            float b1 = alb[j1];
            float2* r1 = (float2*)(a_t + j1*APAD);
            #pragma unroll
            for (int rp = 0; rp < TI2/2; rp++) {
                float2 o; o.x = lo2(s1[rp]) + b1; o.y = hi2(s1[rp]) + b1;
                r1[rp] = o;
            }
        }
    }
    __syncthreads();

    // ---- softmax over cols, per row. 10 warps cover 32 rows ----
    {
        int warp = t >> 5, lane = t & 31;
        for (int r = warp; r < TI2; r += 10) {
            float m = -1e30f;
            for (int j = lane; j < NPIX; j += 32) m = fmaxf(m, a_t[j*APAD + r]);
            #pragma unroll
            for (int o = 16; o; o >>= 1) m = fmaxf(m, __shfl_xor_sync(0xffffffffu, m, o));
            float sum = 0.f;
            for (int j = lane; j < NPIX; j += 32) {
                float e = __expf(a_t[j*APAD + r] - m);
                a_t[j*APAD + r] = e;
                sum += e;
            }
            #pragma unroll
            for (int o = 16; o; o >>= 1) sum += __shfl_xor_sync(0xffffffffu, sum, o);
            float inv = 1.f / sum;
            for (int j = lane; j < NPIX; j += 32) a_t[j*APAD + r] *= inv;
        }
    }
    __syncthreads();

    // ---- E stage: E = P @ V. thread = (d-pair dp = lane, row-group rg = warp) ----
    {
        int dp = t & 31, rg = t >> 5;           // rg in 0..9
        unsigned long long e[4] = {0ull, 0ull, 0ull, 0ull};
        int nr = (rg < 2) ? 4 : 3;              // rows rg + 10*q < 32
        for (int j = 0; j < NPIX; j++) {
            unsigned long long v = ((const unsigned long long*)(Vb + j*DH))[dp];
            #pragma unroll
            for (int q = 0; q < 4; q++) {
                if (q < nr) {
                    unsigned long long a2 = dup2(a_t[j*APAD + rg + 10*q]);
                    ffma2(e[q], v, a2);
                }
            }
        }
        #pragma unroll
        for (int q = 0; q < 4; q++) {
            if (q < nr) {
                int r = rg + 10*q;
                int p = p0 + r;
                if (p < NPIX) {
                    float2 o; o.x = lo2(e[q]); o.y = hi2(e[q]);
                    *(float2*)(g_E + (bb*NPIX + p)*256 + h*DH + 2*dp) = o;
                }
            }
        }
    }
}

// ---------------- lin1 + relu ----------------
__global__ void lin1_kernel(const float* __restrict__ w, const float* __restrict__ b) {
    int idx = blockIdx.x * blockDim.x + threadIdx.x;
    if (idx >= NB*NPIX*DH) return;
    int d = idx & 63;
    int bp = idx >> 6;
    const float* e = g_E + bp*256;
    float acc = b[d];
    #pragma unroll 8
    for (int c = 0; c < 256; c++) acc += e[c] * w[c*DH + d];
    g_F[idx] = fmaxf(acc, 0.f);
}

// ---------------- LN2 stats (per b over 596*64, float accum) ----------------
__global__ void ln2_stats_kernel() {
    int bb = blockIdx.x;
    const float* base = g_F + bb*NPIX*DH;
    const int n = NPIX*DH;
    float s = 0.f, ss = 0.f;
    for (int i = threadIdx.x; i < n; i += blockDim.x) {
        float v = base[i]; s += v; ss += v*v;
    }
    __shared__ double sh[256], sh2[256];
    sh[threadIdx.x] = (double)s; sh2[threadIdx.x] = (double)ss; __syncthreads();
    for (int o = 128; o; o >>= 1) {
        if (threadIdx.x < o) { sh[threadIdx.x] += sh[threadIdx.x+o]; sh2[threadIdx.x] += sh2[threadIdx.x+o]; }
        __syncthreads();
    }
    if (threadIdx.x == 0) {
        double m = sh[0] / (double)n;
        double var = sh2[0] / (double)n - m*m;
        g_mu2[bb] = (float)m;
        g_rv2[bb] = (float)(1.0 / sqrt(var + 1e-5));
    }
}

// ---------------- LN2 apply + max over pixels (256 thr: 4 p-stripes x 64 d) ----------------
__global__ void ln2max_kernel() {
    int bb = blockIdx.x;
    int d = threadIdx.x & 63, pc = threadIdx.x >> 6;
    float mu = g_mu2[bb], rv = g_rv2[bb];
    float m = -1e30f;
    for (int p = pc; p < NPIX; p += 4) {
        float v = (g_F[(bb*NPIX + p)*DH + d] - mu) * rv;
        m = fmaxf(m, v);
    }
    __shared__ float sh[256];
    sh[threadIdx.x] = m; __syncthreads();
    if (pc == 0) {
        m = fmaxf(fmaxf(sh[d], sh[64+d]), fmaxf(sh[128+d], sh[192+d]));
        g_M[bb*DH + d] = m;
    }
}

// ---------------- final lin2 + elu ----------------
__global__ void final_kernel(const float* __restrict__ w, const float* __restrict__ b,
                             float* __restrict__ out) {
    int idx = blockIdx.x * blockDim.x + threadIdx.x;
    if (idx >= NB*10) return;
    int bb = idx / 10, j = idx % 10;
    float acc = b[j];
    #pragma unroll
    for (int d = 0; d < DH; d++) acc += g_M[bb*DH + d] * w[d*10 + j];
    out[idx] = eluf(acc);
}

extern "C" void kernel_launch(void* const* d_in, const int* in_sizes, int n_in,
                              void* d_out, int out_size) {
    const float* x       = (const float*)d_in[0];
    const float* conv1_w = (const float*)d_in[1];
    const float* conv1_b = (const float*)d_in[2];
    const float* conv2_w = (const float*)d_in[3];
    const float* conv2_b = (const float*)d_in[4];
    const float* kp_w    = (const float*)d_in[5];
    const float* kp_b    = (const float*)d_in[6];
    const float* qp_w    = (const float*)d_in[7];
    const float* qp_b    = (const float*)d_in[8];
    const float* vp_w    = (const float*)d_in[9];
    const float* vp_b    = (const float*)d_in[10];
    const float* klin_w  = (const float*)d_in[11];
    const float* klin_b  = (const float*)d_in[12];
    const float* qlin_w  = (const float*)d_in[13];
    const float* qlin_b  = (const float*)d_in[14];
    const float* alin_w  = (const float*)d_in[15];
    const float* alin_b  = (const float*)d_in[16];
    const float* knorm_g = (const float*)d_in[17];
    const float* knorm_b = (const float*)d_in[18];
    const float* qnorm_g = (const float*)d_in[19];
    const float* qnorm_b = (const float*)d_in[20];
    const float* vnorm_g = (const float*)d_in[21];
    const float* vnorm_b = (const float*)d_in[22];
    const float* lin1_w  = (const float*)d_in[23];
    const float* lin1_b  = (const float*)d_in[24];
    const float* lin2_w  = (const float*)d_in[25];
    const float* lin2_b  = (const float*)d_in[26];
    float* out = (float*)d_out;

    cudaFuncSetAttribute(attn_kernel, cudaFuncAttributeMaxDynamicSharedMemorySize, SMEM_BYTES);

    conv1_kernel<<<(NB*16*150*5 + 255)/256, 256>>>(x, conv1_w, conv1_b);
    conv2_feats_kernel<<<(NB*NPIX*34 + 255)/256, 256>>>(conv2_w, conv2_b);
    {
        dim3 g((NB*NPIX*256 + 255)/256, 3);
        proj_kernel<<<g, 256>>>(kp_w, kp_b, qp_w, qp_b, vp_w, vp_b);
    }
    {
        dim3 g(NB, 3);
        ln_stats_kernel<<<g, 256>>>();
    }
    {
        dim3 g(4096, 3);
        ln_apply_kernel<<<g, 256>>>(knorm_g, knorm_b, qnorm_g, qnorm_b, vnorm_g, vnorm_b);
    }
    {
        dim3 g((NPIX + TI2 - 1)/TI2, HEADS, NB);  // (19, 4, 64)
        attn_kernel<<<g, ATHR, SMEM_BYTES>>>(qlin_w, qlin_b, klin_w, klin_b, alin_w, alin_b);
    }
    lin1_kernel<<<(NB*NPIX*DH + 255)/256, 256>>>(lin1_w, lin1_b);
    ln2_stats_kernel<<<NB, 256>>>();
    ln2max_kernel<<<NB, 256>>>();
    final_kernel<<<3, 256>>>(lin2_w, lin2_b, out);
}